// round 4
// baseline (speedup 1.0000x reference)
#include <cuda_runtime.h>
#include <cstdint>

#define BATCH 2
#define SEQ 4096
#define DIM 768
#define NH 12
#define HD 64
#define ROWS (BATCH*SEQ)
#define LOG2E 1.4426950408889634f

// Scratch (allocation-free rule: __device__ globals)
__device__ float g_Q[(size_t)BATCH*NH*SEQ*HD];
__device__ float g_K[(size_t)BATCH*NH*SEQ*HD];
__device__ float g_V[(size_t)BATCH*NH*SEQ*HD];
__device__ float g_AO[(size_t)ROWS*DIM];
__device__ float g_Xr[(size_t)ROWS*DIM];          // X pre-rounded to tf32
__device__ float g_Wt[(size_t)4*DIM*DIM];         // Wq,Wk,Wv,Wo transposed [n][k], tf32

__device__ __forceinline__ unsigned f2tf(float f) {
    unsigned u;
    asm("cvt.rna.tf32.f32 %0, %1;" : "=r"(u) : "f"(f));
    return u;
}

__device__ __forceinline__ float ex2(float x) {
    float y;
    asm("ex2.approx.f32 %0, %1;" : "=f"(y) : "f"(x));
    return y;
}

__device__ __forceinline__ float tftrunc(float f) {
    return __uint_as_float(__float_as_uint(f) & 0xffffe000u);
}

__device__ __forceinline__ void mma8(float d[4], const unsigned a[4],
                                     unsigned b0, unsigned b1) {
    asm volatile(
        "mma.sync.aligned.m16n8k8.row.col.f32.tf32.tf32.f32 "
        "{%0,%1,%2,%3}, {%4,%5,%6,%7}, {%8,%9}, {%0,%1,%2,%3};"
        : "+f"(d[0]), "+f"(d[1]), "+f"(d[2]), "+f"(d[3])
        : "r"(a[0]), "r"(a[1]), "r"(a[2]), "r"(a[3]), "r"(b0), "r"(b1));
}

__device__ __forceinline__ void ldsm4(unsigned r[4], const float* p) {
    unsigned a = (unsigned)__cvta_generic_to_shared(p);
    asm volatile("ldmatrix.sync.aligned.m8n8.x4.b16 {%0,%1,%2,%3}, [%4];"
        : "=r"(r[0]), "=r"(r[1]), "=r"(r[2]), "=r"(r[3]) : "r"(a) : "memory");
}

__device__ __forceinline__ void cp_async16(float* smem_dst, const float* gsrc) {
    unsigned s = (unsigned)__cvta_generic_to_shared(smem_dst);
    asm volatile("cp.async.cg.shared.global [%0], [%1], 16;\n" :: "r"(s), "l"(gsrc));
}

// ---------------------------------------------------------------------------
// Prep kernels
// ---------------------------------------------------------------------------
__global__ __launch_bounds__(256) void round_x_kernel(const float* __restrict__ X)
{
    size_t i = ((size_t)blockIdx.x*256 + threadIdx.x) * 4;
    float4 v = *(const float4*)(X + i);
    float4 o;
    o.x = __uint_as_float(f2tf(v.x));
    o.y = __uint_as_float(f2tf(v.y));
    o.z = __uint_as_float(f2tf(v.z));
    o.w = __uint_as_float(f2tf(v.w));
    *(float4*)(g_Xr + i) = o;
}

__global__ __launch_bounds__(256) void transpose_w_kernel(
    const float* __restrict__ Wq, const float* __restrict__ Wk,
    const float* __restrict__ Wv, const float* __restrict__ Wo)
{
    __shared__ float ts[32][33];
    const float* W = (blockIdx.z == 0) ? Wq : (blockIdx.z == 1) ? Wk
                   : (blockIdx.z == 2) ? Wv : Wo;
    float* Wt = g_Wt + (size_t)blockIdx.z*DIM*DIM;
    int tx = threadIdx.x & 31, ty = threadIdx.x >> 5;   // 32 x 8
    int bx = blockIdx.x * 32, by = blockIdx.y * 32;
#pragma unroll
    for (int i = 0; i < 32; i += 8)
        ts[ty + i][tx] = W[(size_t)(by + ty + i)*DIM + bx + tx];
    __syncthreads();
#pragma unroll
    for (int i = 0; i < 32; i += 8)
        Wt[(size_t)(bx + ty + i)*DIM + by + tx] =
            __uint_as_float(f2tf(ts[tx][ty + i]));
}

// ---------------------------------------------------------------------------
// Raw-mma GEMM with ldmatrix fragment loads.
//   MODE 0: QKV (blockIdx.z selects matrix); Q scaled by 0.125*log2e.
//   MODE 1: O-proj, fp32 + bias -> out.
// ---------------------------------------------------------------------------
#define GSTR 36
#define GEMM_SMEM_BYTES (2*(128*GSTR + 128*GSTR)*4)

template<int MODE>
__global__ __launch_bounds__(256) void gemm128_kernel(
    const float* __restrict__ A, const float* __restrict__ Wt0,
    const float* __restrict__ bq, const float* __restrict__ bk,
    const float* __restrict__ bv, float* __restrict__ out)
{
    extern __shared__ float sm[];
    float* As = sm;                    // 2 x 128 x GSTR
    float* Bs = sm + 2*128*GSTR;       // 2 x 128 x GSTR

    const int t = threadIdx.x;
    const int w = t >> 5, l = t & 31;
    const int g = l >> 2, q4 = l & 3;
    const int lrow  = l & 15;
    const int lcol4 = (l & 16) ? 4 : 0;
    const int krow  = (l & 7) + ((l & 16) ? 8 : 0);
    const int kcol4 = (l & 8) ? 4 : 0;
    const int m0 = blockIdx.y * 128;
    const int n0 = blockIdx.x * 128;
    const int wsel = (MODE == 0) ? blockIdx.z : 0;
    const float* Wt = Wt0 + (size_t)wsel*DIM*DIM;
    const float* bias = (MODE == 1) ? bq : ((wsel == 0) ? bq : (wsel == 1) ? bk : bv);

    const int m0w = (w >> 1) * 32;
    const int n0w = (w & 1) * 64;

#define G_ISSUE(KT, BUF) do {                                                  \
        int k0_ = (KT) * 32;                                                   \
        float* ad_ = As + (BUF)*128*GSTR;                                      \
        float* bd_ = Bs + (BUF)*128*GSTR;                                      \
        for (int i_ = t; i_ < 1024; i_ += 256) {                               \
            int r_ = i_ >> 3, c_ = (i_ & 7) << 2;                              \
            cp_async16(ad_ + r_*GSTR + c_, A  + (size_t)(m0 + r_)*DIM + k0_ + c_); \
            cp_async16(bd_ + r_*GSTR + c_, Wt + (size_t)(n0 + r_)*DIM + k0_ + c_); \
        }                                                                       \
        asm volatile("cp.async.commit_group;\n");                               \
    } while (0)

    float acc[2][8][4];
#pragma unroll
    for (int s = 0; s < 2; s++)
#pragma unroll
        for (int nf = 0; nf < 8; nf++)
#pragma unroll
            for (int e = 0; e < 4; e++) acc[s][nf][e] = 0.f;

    G_ISSUE(0, 0);

    const int NKT = DIM / 32;    // 24
    for (int kt = 0; kt < NKT; kt++) {
        const int buf = kt & 1;
        if (kt + 1 < NKT) {
            G_ISSUE(kt + 1, buf ^ 1);
            asm volatile("cp.async.wait_group 1;\n");
        } else {
            asm volatile("cp.async.wait_group 0;\n");
        }
        __syncthreads();

        const float* a_ = As + buf*128*GSTR;
        const float* b_ = Bs + buf*128*GSTR;

#pragma unroll
        for (int ks = 0; ks < 4; ks++) {
            unsigned af[2][4];
            ldsm4(af[0], a_ + (m0w      + lrow)*GSTR + ks*8 + lcol4);
            ldsm4(af[1], a_ + (m0w + 16 + lrow)*GSTR + ks*8 + lcol4);
#pragma unroll
            for (int np = 0; np < 4; np++) {
                unsigned bf[4];
                ldsm4(bf, b_ + (n0w + np*16 + krow)*GSTR + ks*8 + kcol4);
                mma8(acc[0][2*np],   af[0], bf[0], bf[1]);
                mma8(acc[1][2*np],   af[1], bf[0], bf[1]);
                mma8(acc[0][2*np+1], af[0], bf[2], bf[3]);
                mma8(acc[1][2*np+1], af[1], bf[2], bf[3]);
            }
        }
        __syncthreads();
    }

    // epilogue
#pragma unroll
    for (int s = 0; s < 2; s++) {
#pragma unroll
        for (int nf = 0; nf < 8; nf++) {
            int m  = m0 + m0w + s*16 + g;
            int nn = n0 + n0w + nf*8 + 2*q4;
            float v0 = acc[s][nf][0] + bias[nn];
            float v1 = acc[s][nf][1] + bias[nn + 1];
            float v2 = acc[s][nf][2] + bias[nn];
            float v3 = acc[s][nf][3] + bias[nn + 1];
            if (MODE == 1) {
                float2 p0; p0.x = v0; p0.y = v1;
                float2 p1; p1.x = v2; p1.y = v3;
                *(float2*)(out + (size_t)m*DIM + nn)       = p0;
                *(float2*)(out + (size_t)(m + 8)*DIM + nn) = p1;
            } else {
                float sc = (wsel == 0) ? (0.125f * LOG2E) : 1.0f;
                float* dst = (wsel == 0) ? g_Q : (wsel == 1) ? g_K : g_V;
                int bb = m >> 12, sq = m & 4095;
                int hh = nn >> 6, d = nn & 63;
                size_t base = ((size_t)(bb*NH + hh)*SEQ + sq)*HD + d;
                float2 p0, p1;
                p0.x = __uint_as_float(f2tf(v0 * sc));
                p0.y = __uint_as_float(f2tf(v1 * sc));
                p1.x = __uint_as_float(f2tf(v2 * sc));
                p1.y = __uint_as_float(f2tf(v3 * sc));
                *(float2*)(dst + base)          = p0;
                *(float2*)(dst + base + 8*HD)   = p1;
            }
        }
    }
}

// ---------------------------------------------------------------------------
// Flash attention v3: ldmatrix fragments, P through dead-K smem (swizzled),
// exp2-domain softmax. Q arrives pre-scaled by 0.125*log2e, all inputs tf32.
// ---------------------------------------------------------------------------
#define QSTRIDE 68
#define KSTRIDE 68
#define VSTRIDE 72
#define ATTN3_SMEM_BYTES ((128*QSTRIDE + 2*64*KSTRIDE + 2*64*VSTRIDE) * 4)

// swizzled P offset: row r (0..31 per warp region), col c (0..31):
// off = r*32 + (((c>>2) ^ (r&7))<<2) + (c&3)
__device__ __forceinline__ int p_off(int r, int c) {
    return r*32 + ((((c >> 2) ^ (r & 7))) << 2) + (c & 3);
}

__global__ __launch_bounds__(128) void attn_kernel3()
{
    extern __shared__ float sm[];
    float* Qs = sm;                      // 128 x QSTRIDE
    float* Ks = sm + 128*QSTRIDE;        // 2 x 64 x KSTRIDE
    float* Vs = Ks + 2*64*KSTRIDE;       // 2 x 64 x VSTRIDE

    const int t  = threadIdx.x;
    const int w  = t >> 5;
    const int l  = t & 31;
    const int q4 = l & 3;
    const int g  = l >> 2;
    const int lrow  = l & 15;
    const int lcol4 = (l & 16) ? 4 : 0;
    const int krow  = (l & 7) + ((l & 16) ? 8 : 0);
    const int kcol4 = (l & 8) ? 4 : 0;
    const int qt = blockIdx.x, h = blockIdx.y, b = blockIdx.z;

    const size_t headoff = (size_t)(b*NH + h)*SEQ*HD;
    const float* Qg = g_Q + headoff + (size_t)qt*128*HD;
    const float* Kg = g_K + headoff;
    const float* Vg = g_V + headoff;

    for (int i = t; i < 128*16; i += 128) {
        int r = i >> 4, c = (i & 15) << 2;
        *(float4*)(Qs + r*QSTRIDE + c) = *(const float4*)(Qg + (size_t)r*HD + c);
    }

#define ISSUE_TILE(KT, BUF) do {                                          \
        const float* kp_ = Kg + (size_t)(KT)*64*HD;                        \
        const float* vp_ = Vg + (size_t)(KT)*64*HD;                        \
        float* kd_ = Ks + (BUF)*64*KSTRIDE;                                \
        float* vd_ = Vs + (BUF)*64*VSTRIDE;                                \
        for (int i_ = t; i_ < 1024; i_ += 128) {                           \
            int r_ = i_ >> 4, c_ = (i_ & 15) << 2;                         \
            cp_async16(kd_ + r_*KSTRIDE + c_, kp_ + (size_t)r_*HD + c_);   \
            cp_async16(vd_ + r_*VSTRIDE + c_, vp_ + (size_t)r_*HD + c_);   \
        }                                                                  \
        asm volatile("cp.async.commit_group;\n");                          \
    } while (0)

    float of[2][8][4];
#pragma unroll
    for (int s = 0; s < 2; s++)
#pragma unroll
        for (int nf = 0; nf < 8; nf++)
#pragma unroll
            for (int e = 0; e < 4; e++) of[s][nf][e] = 0.f;
    float mrun[2][2] = {{-1e30f, -1e30f}, {-1e30f, -1e30f}};
    float lrun[2][2] = {{0.f, 0.f}, {0.f, 0.f}};

    const int rbase = w * 32;

    ISSUE_TILE(0, 0);

    const int NT = SEQ / 64;
    for (int kt = 0; kt < NT; kt++) {
        const int buf = kt & 1;
        if (kt + 1 < NT) {
            ISSUE_TILE(kt + 1, buf ^ 1);
            asm volatile("cp.async.wait_group 1;\n");
        } else {
            asm volatile("cp.async.wait_group 0;\n");
        }
        __syncthreads();

        const float* kb_ = Ks + buf*64*KSTRIDE;
        const float* vb_ = Vs + buf*64*VSTRIDE;

        // ---- S = Q K^T (ldmatrix fragments) ----
        float sf[2][8][4];
#pragma unroll
        for (int s = 0; s < 2; s++)
#pragma unroll
            for (int nf = 0; nf < 8; nf++)
#pragma unroll
                for (int e = 0; e < 4; e++) sf[s][nf][e] = 0.f;

#pragma unroll
        for (int ks = 0; ks < 8; ks++) {
            unsigned qa[2][4];
            ldsm4(qa[0], Qs + (rbase      + lrow)*QSTRIDE + ks*8 + lcol4);
            ldsm4(qa[1], Qs + (rbase + 16 + lrow)*QSTRIDE + ks*8 + lcol4);
#pragma unroll
            for (int np = 0; np < 4; np++) {
                unsigned bf[4];
                ldsm4(bf, kb_ + (np*16 + krow)*KSTRIDE + ks*8 + kcol4);
                mma8(sf[0][2*np],   qa[0], bf[0], bf[1]);
                mma8(sf[1][2*np],   qa[1], bf[0], bf[1]);
                mma8(sf[0][2*np+1], qa[0], bf[2], bf[3]);
                mma8(sf[1][2*np+1], qa[1], bf[2], bf[3]);
            }
        }

        // ---- online softmax (exp2 domain, tf32-consistent truncation) ----
#pragma unroll
        for (int s = 0; s < 2; s++) {
            float mx0 = -1e30f, mx1 = -1e30f;
#pragma unroll
            for (int nf = 0; nf < 8; nf++) {
                mx0 = fmaxf(mx0, fmaxf(sf[s][nf][0], sf[s][nf][1]));
                mx1 = fmaxf(mx1, fmaxf(sf[s][nf][2], sf[s][nf][3]));
            }
            mx0 = fmaxf(mx0, __shfl_xor_sync(0xffffffffu, mx0, 1));
            mx0 = fmaxf(mx0, __shfl_xor_sync(0xffffffffu, mx0, 2));
            mx1 = fmaxf(mx1, __shfl_xor_sync(0xffffffffu, mx1, 1));
            mx1 = fmaxf(mx1, __shfl_xor_sync(0xffffffffu, mx1, 2));
            float mn0 = fmaxf(mrun[s][0], mx0);
            float mn1 = fmaxf(mrun[s][1], mx1);
            float a0 = ex2(mrun[s][0] - mn0);
            float a1 = ex2(mrun[s][1] - mn1);
            mrun[s][0] = mn0; mrun[s][1] = mn1;
            float sum0 = 0.f, sum1 = 0.f;
#pragma unroll
            for (int nf = 0; nf < 8; nf++) {
                float p0 = tftrunc(ex2(sf[s][nf][0] - mn0));
                float p1 = tftrunc(ex2(sf[s][nf][1] - mn0));
                float p2 = tftrunc(ex2(sf[s][nf][2] - mn1));
                float p3 = tftrunc(ex2(sf[s][nf][3] - mn1));
                sum0 += p0 + p1; sum1 += p2 + p3;
                sf[s][nf][0] = p0; sf[s][nf][1] = p1;
                sf[s][nf][2] = p2; sf[s][nf][3] = p3;
            }
            sum0 += __shfl_xor_sync(0xffffffffu, sum0, 1);
            sum0 += __shfl_xor_sync(0xffffffffu, sum0, 2);
            sum1 += __shfl_xor_sync(0xffffffffu, sum1, 1);
            sum1 += __shfl_xor_sync(0xffffffffu, sum1, 2);
            lrun[s][0] = lrun[s][0]*a0 + sum0;
            lrun[s][1] = lrun[s][1]*a1 + sum1;
#pragma unroll
            for (int nf = 0; nf < 8; nf++) {
                of[s][nf][0] *= a0; of[s][nf][1] *= a0;
                of[s][nf][2] *= a1; of[s][nf][3] *= a1;
            }
        }

        // all warps finished reading K[buf]; its space becomes the P buffer
        __syncthreads();
        float* Pw = Ks + buf*64*KSTRIDE + w*32*32;   // per-warp 32x32 swizzled

        // ---- O += P V in two 32-key halves through smem ----
#pragma unroll
        for (int h2 = 0; h2 < 2; h2++) {
#pragma unroll
            for (int s = 0; s < 2; s++) {
#pragma unroll
                for (int j = 0; j < 4; j++) {
                    int nf = h2*4 + j;
                    float2 lo; lo.x = sf[s][nf][0]; lo.y = sf[s][nf][1];
                    float2 hi; hi.x = sf[s][nf][2]; hi.y = sf[s][nf][3];
                    *(float2*)(Pw + p_off(s*16 + g,     j*8 + 2*q4)) = lo;
                    *(float2*)(Pw + p_off(s*16 + g + 8, j*8 + 2*q4)) = hi;
                }
            }
            __syncwarp();
#pragma unroll
            for (int k2 = 0; k2 < 4; k2++) {
                unsigned pa[2][4];
                {
                    int r0 = lrow;
                    int c0 = k2*8 + lcol4;
                    ldsm4(pa[0], Pw + r0*32 + ((((c0 >> 2) ^ (r0 & 7))) << 2));
                    int r1 = 16 + lrow;
                    ldsm4(pa[1], Pw + r1*32 + ((((c0 >> 2) ^ (r1 & 7))) << 2));
                }
                int ks = h2*4 + k2;
#pragma unroll
                for (int nf = 0; nf < 8; nf++) {
                    const float* vrow = vb_ + (ks*8 + q4)*VSTRIDE + nf*8 + g;
                    unsigned b0 = __float_as_uint(vrow[0]);
                    unsigned b1 = __float_as_uint(vrow[4*VSTRIDE]);
                    mma8(of[0][nf], pa[0], b0, b1);
                    mma8(of[1][nf], pa[1], b0, b1);
                }
            }
            __syncwarp();
        }
        __syncthreads();
    }

    // ---- epilogue: normalize, round to tf32 for the O-proj, write [B,S,D] ----
#pragma unroll
    for (int s = 0; s < 2; s++) {
        float inv0 = 1.f / lrun[s][0];
        float inv1 = 1.f / lrun[s][1];
        int r0 = qt*128 + rbase + s*16 + g;
#pragma unroll
        for (int nf = 0; nf < 8; nf++) {
            int col = h*64 + nf*8 + 2*q4;
            float2 p0, p1;
            p0.x = __uint_as_float(f2tf(of[s][nf][0]*inv0));
            p0.y = __uint_as_float(f2tf(of[s][nf][1]*inv0));
            p1.x = __uint_as_float(f2tf(of[s][nf][2]*inv1));
            p1.y = __uint_as_float(f2tf(of[s][nf][3]*inv1));
            *(float2*)(g_AO + ((size_t)b*SEQ + r0    )*DIM + col) = p0;
            *(float2*)(g_AO + ((size_t)b*SEQ + r0 + 8)*DIM + col) = p1;
        }
    }
}

// ---------------------------------------------------------------------------
extern "C" void kernel_launch(void* const* d_in, const int* in_sizes, int n_in,
                              void* d_out, int out_size)
{
    (void)in_sizes; (void)n_in; (void)out_size;
    const float* x  = (const float*)d_in[0];
    const float* Wq = (const float*)d_in[1];
    const float* bq = (const float*)d_in[2];
    const float* Wk = (const float*)d_in[3];
    const float* bk = (const float*)d_in[4];
    const float* Wv = (const float*)d_in[5];
    const float* bv = (const float*)d_in[6];
    const float* Wo = (const float*)d_in[7];
    const float* bo = (const float*)d_in[8];
    float* out = (float*)d_out;

    cudaFuncSetAttribute(attn_kernel3,
                         cudaFuncAttributeMaxDynamicSharedMemorySize,
                         ATTN3_SMEM_BYTES);
    cudaFuncSetAttribute(gemm128_kernel<0>,
                         cudaFuncAttributeMaxDynamicSharedMemorySize,
                         GEMM_SMEM_BYTES);
    cudaFuncSetAttribute(gemm128_kernel<1>,
                         cudaFuncAttributeMaxDynamicSharedMemorySize,
                         GEMM_SMEM_BYTES);

    round_x_kernel<<<ROWS*DIM/(256*4), 256>>>(x);
    transpose_w_kernel<<<dim3(24, 24, 4), 256>>>(Wq, Wk, Wv, Wo);

    float* g_Wt_ptr;
    cudaGetSymbolAddress((void**)&g_Wt_ptr, g_Wt);
    float* g_Xr_ptr;
    cudaGetSymbolAddress((void**)&g_Xr_ptr, g_Xr);
    float* g_AO_ptr;
    cudaGetSymbolAddress((void**)&g_AO_ptr, g_AO);

    gemm128_kernel<0><<<dim3(6, 64, 3), 256, GEMM_SMEM_BYTES>>>(
        g_Xr_ptr, g_Wt_ptr, bq, bk, bv, nullptr);

    attn_kernel3<<<dim3(SEQ/128, NH, BATCH), 128, ATTN3_SMEM_BYTES>>>();

    gemm128_kernel<1><<<dim3(6, 64, 1), 256, GEMM_SMEM_BYTES>>>(
        g_AO_ptr, g_Wt_ptr + (size_t)3*DIM*DIM, bo, nullptr, nullptr, out);
}

// round 5
// speedup vs baseline: 1.0241x; 1.0241x over previous
#include <cuda_runtime.h>
#include <cstdint>

#define BATCH 2
#define SEQ 4096
#define DIM 768
#define NH 12
#define HD 64
#define ROWS (BATCH*SEQ)
#define LOG2E 1.4426950408889634f

// Scratch (allocation-free rule: __device__ globals)
__device__ float g_Q[(size_t)BATCH*NH*SEQ*HD];
__device__ float g_K[(size_t)BATCH*NH*SEQ*HD];
__device__ float g_Vt[(size_t)BATCH*NH*HD*SEQ];   // V transposed: [B,H,d,s]
__device__ float g_AO[(size_t)ROWS*DIM];
__device__ float g_Xr[(size_t)ROWS*DIM];          // X pre-rounded to tf32
__device__ float g_Wt[(size_t)4*DIM*DIM];         // Wq,Wk,Wv,Wo transposed [n][k], tf32

__device__ __forceinline__ unsigned f2tf(float f) {
    unsigned u;
    asm("cvt.rna.tf32.f32 %0, %1;" : "=r"(u) : "f"(f));
    return u;
}

__device__ __forceinline__ float ex2(float x) {
    float y;
    asm("ex2.approx.f32 %0, %1;" : "=f"(y) : "f"(x));
    return y;
}

__device__ __forceinline__ float tftrunc(float f) {
    return __uint_as_float(__float_as_uint(f) & 0xffffe000u);
}

__device__ __forceinline__ void mma8(float d[4], const unsigned a[4],
                                     unsigned b0, unsigned b1) {
    asm volatile(
        "mma.sync.aligned.m16n8k8.row.col.f32.tf32.tf32.f32 "
        "{%0,%1,%2,%3}, {%4,%5,%6,%7}, {%8,%9}, {%0,%1,%2,%3};"
        : "+f"(d[0]), "+f"(d[1]), "+f"(d[2]), "+f"(d[3])
        : "r"(a[0]), "r"(a[1]), "r"(a[2]), "r"(a[3]), "r"(b0), "r"(b1));
}

__device__ __forceinline__ void ldsm4(unsigned r[4], const float* p) {
    unsigned a = (unsigned)__cvta_generic_to_shared(p);
    asm volatile("ldmatrix.sync.aligned.m8n8.x4.b16 {%0,%1,%2,%3}, [%4];"
        : "=r"(r[0]), "=r"(r[1]), "=r"(r[2]), "=r"(r[3]) : "r"(a) : "memory");
}

__device__ __forceinline__ void cp_async16(float* smem_dst, const float* gsrc) {
    unsigned s = (unsigned)__cvta_generic_to_shared(smem_dst);
    asm volatile("cp.async.cg.shared.global [%0], [%1], 16;\n" :: "r"(s), "l"(gsrc));
}

// ---------------------------------------------------------------------------
// Prep kernels
// ---------------------------------------------------------------------------
__global__ __launch_bounds__(256) void round_x_kernel(const float* __restrict__ X)
{
    size_t i = ((size_t)blockIdx.x*256 + threadIdx.x) * 4;
    float4 v = *(const float4*)(X + i);
    float4 o;
    o.x = __uint_as_float(f2tf(v.x));
    o.y = __uint_as_float(f2tf(v.y));
    o.z = __uint_as_float(f2tf(v.z));
    o.w = __uint_as_float(f2tf(v.w));
    *(float4*)(g_Xr + i) = o;
}

__global__ __launch_bounds__(256) void transpose_w_kernel(
    const float* __restrict__ Wq, const float* __restrict__ Wk,
    const float* __restrict__ Wv, const float* __restrict__ Wo)
{
    __shared__ float ts[32][33];
    const float* W = (blockIdx.z == 0) ? Wq : (blockIdx.z == 1) ? Wk
                   : (blockIdx.z == 2) ? Wv : Wo;
    float* Wt = g_Wt + (size_t)blockIdx.z*DIM*DIM;
    int tx = threadIdx.x & 31, ty = threadIdx.x >> 5;   // 32 x 8
    int bx = blockIdx.x * 32, by = blockIdx.y * 32;
#pragma unroll
    for (int i = 0; i < 32; i += 8)
        ts[ty + i][tx] = W[(size_t)(by + ty + i)*DIM + bx + tx];
    __syncthreads();
#pragma unroll
    for (int i = 0; i < 32; i += 8)
        Wt[(size_t)(bx + ty + i)*DIM + by + tx] =
            __uint_as_float(f2tf(ts[tx][ty + i]));
}

// ---------------------------------------------------------------------------
// Raw-mma GEMM with ldmatrix fragment loads.
//   MODE 0: QKV (blockIdx.z selects matrix); Q scaled by 0.125*log2e,
//           V written TRANSPOSED to g_Vt[b,h,d,s].
//   MODE 1: O-proj, fp32 + bias -> out.
// ---------------------------------------------------------------------------
#define GSTR 36
#define GEMM_SMEM_BYTES (2*(128*GSTR + 128*GSTR)*4)

template<int MODE>
__global__ __launch_bounds__(256) void gemm128_kernel(
    const float* __restrict__ A, const float* __restrict__ Wt0,
    const float* __restrict__ bq, const float* __restrict__ bk,
    const float* __restrict__ bv, float* __restrict__ out)
{
    extern __shared__ float sm[];
    float* As = sm;                    // 2 x 128 x GSTR
    float* Bs = sm + 2*128*GSTR;       // 2 x 128 x GSTR

    const int t = threadIdx.x;
    const int w = t >> 5, l = t & 31;
    const int g = l >> 2, q4 = l & 3;
    const int lrow  = l & 15;
    const int lcol4 = (l & 16) ? 4 : 0;
    const int krow  = (l & 7) + ((l & 16) ? 8 : 0);
    const int kcol4 = (l & 8) ? 4 : 0;
    const int m0 = blockIdx.y * 128;
    const int n0 = blockIdx.x * 128;
    const int wsel = (MODE == 0) ? blockIdx.z : 0;
    const float* Wt = Wt0 + (size_t)wsel*DIM*DIM;
    const float* bias = (MODE == 1) ? bq : ((wsel == 0) ? bq : (wsel == 1) ? bk : bv);

    const int m0w = (w >> 1) * 32;
    const int n0w = (w & 1) * 64;

#define G_ISSUE(KT, BUF) do {                                                  \
        int k0_ = (KT) * 32;                                                   \
        float* ad_ = As + (BUF)*128*GSTR;                                      \
        float* bd_ = Bs + (BUF)*128*GSTR;                                      \
        for (int i_ = t; i_ < 1024; i_ += 256) {                               \
            int r_ = i_ >> 3, c_ = (i_ & 7) << 2;                              \
            cp_async16(ad_ + r_*GSTR + c_, A  + (size_t)(m0 + r_)*DIM + k0_ + c_); \
            cp_async16(bd_ + r_*GSTR + c_, Wt + (size_t)(n0 + r_)*DIM + k0_ + c_); \
        }                                                                       \
        asm volatile("cp.async.commit_group;\n");                               \
    } while (0)

    float acc[2][8][4];
#pragma unroll
    for (int s = 0; s < 2; s++)
#pragma unroll
        for (int nf = 0; nf < 8; nf++)
#pragma unroll
            for (int e = 0; e < 4; e++) acc[s][nf][e] = 0.f;

    G_ISSUE(0, 0);

    const int NKT = DIM / 32;    // 24
    for (int kt = 0; kt < NKT; kt++) {
        const int buf = kt & 1;
        if (kt + 1 < NKT) {
            G_ISSUE(kt + 1, buf ^ 1);
            asm volatile("cp.async.wait_group 1;\n");
        } else {
            asm volatile("cp.async.wait_group 0;\n");
        }
        __syncthreads();

        const float* a_ = As + buf*128*GSTR;
        const float* b_ = Bs + buf*128*GSTR;

#pragma unroll
        for (int ks = 0; ks < 4; ks++) {
            unsigned af[2][4];
            ldsm4(af[0], a_ + (m0w      + lrow)*GSTR + ks*8 + lcol4);
            ldsm4(af[1], a_ + (m0w + 16 + lrow)*GSTR + ks*8 + lcol4);
#pragma unroll
            for (int np = 0; np < 4; np++) {
                unsigned bf[4];
                ldsm4(bf, b_ + (n0w + np*16 + krow)*GSTR + ks*8 + kcol4);
                mma8(acc[0][2*np],   af[0], bf[0], bf[1]);
                mma8(acc[1][2*np],   af[1], bf[0], bf[1]);
                mma8(acc[0][2*np+1], af[0], bf[2], bf[3]);
                mma8(acc[1][2*np+1], af[1], bf[2], bf[3]);
            }
        }
        __syncthreads();
    }

    // epilogue
#pragma unroll
    for (int s = 0; s < 2; s++) {
#pragma unroll
        for (int nf = 0; nf < 8; nf++) {
            int m  = m0 + m0w + s*16 + g;
            int nn = n0 + n0w + nf*8 + 2*q4;
            float v0 = acc[s][nf][0] + bias[nn];
            float v1 = acc[s][nf][1] + bias[nn + 1];
            float v2 = acc[s][nf][2] + bias[nn];
            float v3 = acc[s][nf][3] + bias[nn + 1];
            if (MODE == 1) {
                float2 p0; p0.x = v0; p0.y = v1;
                float2 p1; p1.x = v2; p1.y = v3;
                *(float2*)(out + (size_t)m*DIM + nn)       = p0;
                *(float2*)(out + (size_t)(m + 8)*DIM + nn) = p1;
            } else {
                int bb = m >> 12, sq = m & 4095;
                int hh = nn >> 6, d = nn & 63;
                if (wsel == 2) {
                    // V transposed: g_Vt[((bb*NH+hh)*HD + d)*SEQ + sq]
                    size_t bt = ((size_t)(bb*NH + hh)*HD + d)*SEQ + sq;
                    g_Vt[bt]           = __uint_as_float(f2tf(v0));
                    g_Vt[bt + SEQ]     = __uint_as_float(f2tf(v1));
                    g_Vt[bt + 8]       = __uint_as_float(f2tf(v2));
                    g_Vt[bt + SEQ + 8] = __uint_as_float(f2tf(v3));
                } else {
                    float sc = (wsel == 0) ? (0.125f * LOG2E) : 1.0f;
                    float* dst = (wsel == 0) ? g_Q : g_K;
                    size_t base = ((size_t)(bb*NH + hh)*SEQ + sq)*HD + d;
                    float2 p0, p1;
                    p0.x = __uint_as_float(f2tf(v0 * sc));
                    p0.y = __uint_as_float(f2tf(v1 * sc));
                    p1.x = __uint_as_float(f2tf(v2 * sc));
                    p1.y = __uint_as_float(f2tf(v3 * sc));
                    *(float2*)(dst + base)        = p0;
                    *(float2*)(dst + base + 8*HD) = p1;
                }
            }
        }
    }
}

// ---------------------------------------------------------------------------
// Flash attention v5: ldmatrix for Q/K/P AND V (V pre-transposed in gmem),
// P through dead-K smem, exp2-domain softmax. All inputs tf32-pre-rounded.
// ---------------------------------------------------------------------------
#define QSTRIDE 68
#define KSTRIDE 68
#define VTSTR   68
#define ATTN5_SMEM_BYTES ((128*QSTRIDE + 2*64*KSTRIDE + 2*64*VTSTR) * 4)

__device__ __forceinline__ int p_off(int r, int c) {
    return r*32 + ((((c >> 2) ^ (r & 7))) << 2) + (c & 3);
}

__global__ __launch_bounds__(128) void attn_kernel5()
{
    extern __shared__ float sm[];
    float* Qs  = sm;                     // 128 x QSTRIDE
    float* Ks  = sm + 128*QSTRIDE;       // 2 x 64 x KSTRIDE
    float* Vts = Ks + 2*64*KSTRIDE;      // 2 x 64(dims) x VTSTR(keys)

    const int t  = threadIdx.x;
    const int w  = t >> 5;
    const int l  = t & 31;
    const int q4 = l & 3;
    const int g  = l >> 2;
    const int lrow  = l & 15;
    const int lcol4 = (l & 16) ? 4 : 0;
    const int krow  = (l & 7) + ((l & 16) ? 8 : 0);
    const int kcol4 = (l & 8) ? 4 : 0;
    const int qt = blockIdx.x, h = blockIdx.y, b = blockIdx.z;

    const size_t headoff = (size_t)(b*NH + h)*SEQ*HD;
    const float* Qg  = g_Q  + headoff + (size_t)qt*128*HD;
    const float* Kg  = g_K  + headoff;
    const float* Vtg = g_Vt + headoff;   // [d][s] within head

    for (int i = t; i < 128*16; i += 128) {
        int r = i >> 4, c = (i & 15) << 2;
        *(float4*)(Qs + r*QSTRIDE + c) = *(const float4*)(Qg + (size_t)r*HD + c);
    }

#define ISSUE_TILE5(KT, BUF) do {                                           \
        const float* kp_ = Kg + (size_t)(KT)*64*HD;                          \
        const float* vp_ = Vtg + (KT)*64;                                    \
        float* kd_ = Ks  + (BUF)*64*KSTRIDE;                                 \
        float* vd_ = Vts + (BUF)*64*VTSTR;                                   \
        for (int i_ = t; i_ < 1024; i_ += 128) {                             \
            int r_ = i_ >> 4, c_ = (i_ & 15) << 2;                           \
            cp_async16(kd_ + r_*KSTRIDE + c_, kp_ + (size_t)r_*HD + c_);     \
            cp_async16(vd_ + r_*VTSTR  + c_, vp_ + (size_t)r_*SEQ + c_);     \
        }                                                                     \
        asm volatile("cp.async.commit_group;\n");                             \
    } while (0)

    float of[2][8][4];
#pragma unroll
    for (int s = 0; s < 2; s++)
#pragma unroll
        for (int nf = 0; nf < 8; nf++)
#pragma unroll
            for (int e = 0; e < 4; e++) of[s][nf][e] = 0.f;
    float mrun[2][2] = {{-1e30f, -1e30f}, {-1e30f, -1e30f}};
    float lrun[2][2] = {{0.f, 0.f}, {0.f, 0.f}};

    const int rbase = w * 32;

    ISSUE_TILE5(0, 0);

    const int NT = SEQ / 64;
    for (int kt = 0; kt < NT; kt++) {
        const int buf = kt & 1;
        if (kt + 1 < NT) {
            ISSUE_TILE5(kt + 1, buf ^ 1);
            asm volatile("cp.async.wait_group 1;\n");
        } else {
            asm volatile("cp.async.wait_group 0;\n");
        }
        __syncthreads();

        const float* kb_ = Ks  + buf*64*KSTRIDE;
        const float* vb_ = Vts + buf*64*VTSTR;

        // ---- S = Q K^T (ldmatrix fragments) ----
        float sf[2][8][4];
#pragma unroll
        for (int s = 0; s < 2; s++)
#pragma unroll
            for (int nf = 0; nf < 8; nf++)
#pragma unroll
                for (int e = 0; e < 4; e++) sf[s][nf][e] = 0.f;

#pragma unroll
        for (int ks = 0; ks < 8; ks++) {
            unsigned qa[2][4];
            ldsm4(qa[0], Qs + (rbase      + lrow)*QSTRIDE + ks*8 + lcol4);
            ldsm4(qa[1], Qs + (rbase + 16 + lrow)*QSTRIDE + ks*8 + lcol4);
#pragma unroll
            for (int np = 0; np < 4; np++) {
                unsigned bf[4];
                ldsm4(bf, kb_ + (np*16 + krow)*KSTRIDE + ks*8 + kcol4);
                mma8(sf[0][2*np],   qa[0], bf[0], bf[1]);
                mma8(sf[1][2*np],   qa[1], bf[0], bf[1]);
                mma8(sf[0][2*np+1], qa[0], bf[2], bf[3]);
                mma8(sf[1][2*np+1], qa[1], bf[2], bf[3]);
            }
        }

        // ---- online softmax (exp2 domain) ----
#pragma unroll
        for (int s = 0; s < 2; s++) {
            float mx0 = -1e30f, mx1 = -1e30f;
#pragma unroll
            for (int nf = 0; nf < 8; nf++) {
                mx0 = fmaxf(mx0, fmaxf(sf[s][nf][0], sf[s][nf][1]));
                mx1 = fmaxf(mx1, fmaxf(sf[s][nf][2], sf[s][nf][3]));
            }
            mx0 = fmaxf(mx0, __shfl_xor_sync(0xffffffffu, mx0, 1));
            mx0 = fmaxf(mx0, __shfl_xor_sync(0xffffffffu, mx0, 2));
            mx1 = fmaxf(mx1, __shfl_xor_sync(0xffffffffu, mx1, 1));
            mx1 = fmaxf(mx1, __shfl_xor_sync(0xffffffffu, mx1, 2));
            float mn0 = fmaxf(mrun[s][0], mx0);
            float mn1 = fmaxf(mrun[s][1], mx1);
            float a0 = ex2(mrun[s][0] - mn0);
            float a1 = ex2(mrun[s][1] - mn1);
            mrun[s][0] = mn0; mrun[s][1] = mn1;
            float sum0 = 0.f, sum1 = 0.f;
#pragma unroll
            for (int nf = 0; nf < 8; nf++) {
                float p0 = tftrunc(ex2(sf[s][nf][0] - mn0));
                float p1 = tftrunc(ex2(sf[s][nf][1] - mn0));
                float p2 = tftrunc(ex2(sf[s][nf][2] - mn1));
                float p3 = tftrunc(ex2(sf[s][nf][3] - mn1));
                sum0 += p0 + p1; sum1 += p2 + p3;
                sf[s][nf][0] = p0; sf[s][nf][1] = p1;
                sf[s][nf][2] = p2; sf[s][nf][3] = p3;
            }
            sum0 += __shfl_xor_sync(0xffffffffu, sum0, 1);
            sum0 += __shfl_xor_sync(0xffffffffu, sum0, 2);
            sum1 += __shfl_xor_sync(0xffffffffu, sum1, 1);
            sum1 += __shfl_xor_sync(0xffffffffu, sum1, 2);
            lrun[s][0] = lrun[s][0]*a0 + sum0;
            lrun[s][1] = lrun[s][1]*a1 + sum1;
#pragma unroll
            for (int nf = 0; nf < 8; nf++) {
                of[s][nf][0] *= a0; of[s][nf][1] *= a0;
                of[s][nf][2] *= a1; of[s][nf][3] *= a1;
            }
        }

        // all warps finished reading K[buf]; its space becomes the P buffer
        __syncthreads();
        float* Pw = Ks + buf*64*KSTRIDE + w*32*32;   // per-warp 32x32 swizzled

        // ---- O += P V in two 32-key halves; V fragments via ldmatrix ----
#pragma unroll
        for (int h2 = 0; h2 < 2; h2++) {
#pragma unroll
            for (int s = 0; s < 2; s++) {
#pragma unroll
                for (int j = 0; j < 4; j++) {
                    int nf = h2*4 + j;
                    float2 lo; lo.x = sf[s][nf][0]; lo.y = sf[s][nf][1];
                    float2 hi; hi.x = sf[s][nf][2]; hi.y = sf[s][nf][3];
                    *(float2*)(Pw + p_off(s*16 + g,     j*8 + 2*q4)) = lo;
                    *(float2*)(Pw + p_off(s*16 + g + 8, j*8 + 2*q4)) = hi;
                }
            }
            __syncwarp();
#pragma unroll
            for (int k2 = 0; k2 < 4; k2++) {
                unsigned pa[2][4];
                {
                    int c0 = k2*8 + lcol4;
                    int r0 = lrow;
                    ldsm4(pa[0], Pw + r0*32 + ((((c0 >> 2) ^ (r0 & 7))) << 2));
                    int r1 = 16 + lrow;
                    ldsm4(pa[1], Pw + r1*32 + ((((c0 >> 2) ^ (r1 & 7))) << 2));
                }
                int keyoff = h2*32 + k2*8;   // key k-step within the 64-key tile
#pragma unroll
                for (int np = 0; np < 4; np++) {
                    unsigned bf[4];
                    ldsm4(bf, vb_ + (np*16 + krow)*VTSTR + keyoff + kcol4);
                    mma8(of[0][2*np],   pa[0], bf[0], bf[1]);
                    mma8(of[1][2*np],   pa[1], bf[0], bf[1]);
                    mma8(of[0][2*np+1], pa[0], bf[2], bf[3]);
                    mma8(of[1][2*np+1], pa[1], bf[2], bf[3]);
                }
            }
            __syncwarp();
        }
        __syncthreads();
    }

    // ---- epilogue: normalize, round to tf32 for the O-proj, write [B,S,D] ----
#pragma unroll
    for (int s = 0; s < 2; s++) {
        float inv0 = 1.f / lrun[s][0];
        float inv1 = 1.f / lrun[s][1];
        int r0 = qt*128 + rbase + s*16 + g;
#pragma unroll
        for (int nf = 0; nf < 8; nf++) {
            int col = h*64 + nf*8 + 2*q4;
            float2 p0, p1;
            p0.x = __uint_as_float(f2tf(of[s][nf][0]*inv0));
            p0.y = __uint_as_float(f2tf(of[s][nf][1]*inv0));
            p1.x = __uint_as_float(f2tf(of[s][nf][2]*inv1));
            p1.y = __uint_as_float(f2tf(of[s][nf][3]*inv1));
            *(float2*)(g_AO + ((size_t)b*SEQ + r0    )*DIM + col) = p0;
            *(float2*)(g_AO + ((size_t)b*SEQ + r0 + 8)*DIM + col) = p1;
        }
    }
}

// ---------------------------------------------------------------------------
extern "C" void kernel_launch(void* const* d_in, const int* in_sizes, int n_in,
                              void* d_out, int out_size)
{
    (void)in_sizes; (void)n_in; (void)out_size;
    const float* x  = (const float*)d_in[0];
    const float* Wq = (const float*)d_in[1];
    const float* bq = (const float*)d_in[2];
    const float* Wk = (const float*)d_in[3];
    const float* bk = (const float*)d_in[4];
    const float* Wv = (const float*)d_in[5];
    const float* bv = (const float*)d_in[6];
    const float* Wo = (const float*)d_in[7];
    const float* bo = (const float*)d_in[8];
    float* out = (float*)d_out;

    cudaFuncSetAttribute(attn_kernel5,
                         cudaFuncAttributeMaxDynamicSharedMemorySize,
                         ATTN5_SMEM_BYTES);
    cudaFuncSetAttribute(gemm128_kernel<0>,
                         cudaFuncAttributeMaxDynamicSharedMemorySize,
                         GEMM_SMEM_BYTES);
    cudaFuncSetAttribute(gemm128_kernel<1>,
                         cudaFuncAttributeMaxDynamicSharedMemorySize,
                         GEMM_SMEM_BYTES);

    round_x_kernel<<<ROWS*DIM/(256*4), 256>>>(x);
    transpose_w_kernel<<<dim3(24, 24, 4), 256>>>(Wq, Wk, Wv, Wo);

    float* g_Wt_ptr;
    cudaGetSymbolAddress((void**)&g_Wt_ptr, g_Wt);
    float* g_Xr_ptr;
    cudaGetSymbolAddress((void**)&g_Xr_ptr, g_Xr);
    float* g_AO_ptr;
    cudaGetSymbolAddress((void**)&g_AO_ptr, g_AO);

    gemm128_kernel<0><<<dim3(6, 64, 3), 256, GEMM_SMEM_BYTES>>>(
        g_Xr_ptr, g_Wt_ptr, bq, bk, bv, nullptr);

    attn_kernel5<<<dim3(SEQ/128, NH, BATCH), 128, ATTN5_SMEM_BYTES>>>();

    gemm128_kernel<1><<<dim3(6, 64, 1), 256, GEMM_SMEM_BYTES>>>(
        g_AO_ptr, g_Wt_ptr + (size_t)3*DIM*DIM, bo, nullptr, nullptr, out);
}